// round 11
// baseline (speedup 1.0000x reference)
#include <cuda_runtime.h>
#include <cstdint>
#include <cstddef>
#include <algorithm>

// ---------------- problem constants ----------------
#define BB   256        // batch
#define FD   128        // feature dim (also E)
#define DEG  64         // max degree
#define S1N  (BB * 50)  // 12800 rows per chain at hop-1
#define M1   (2 * S1N)  // 25600 rows (both chains) for the big GEMM

// fused kernel smem: A tile 64x384 f32 + B tile 16x128 f32
#define SMEM_FUSED ((64 * 384 + 16 * 128) * 4)

// ---------------- device scratch (static, no runtime alloc) ----------------
__device__ int   g_s1[2][S1N];
__device__ float g_h1  [(size_t)M1 * 128];      // hop1 hidden
__device__ float g_agg0[(size_t)2 * BB * 384];  // hop0 agg
__device__ float g_h0  [(size_t)2 * BB * 128];  // hop0 hidden
__device__ float g_aggL1[(size_t)2 * BB * 384]; // layer-1 agg
__device__ float g_head[3][(size_t)2 * BB * 128]; // mean/std/pi hidden

struct ColsParam {
    int out25[2][25];
    int in25 [2][25];
    int out10[2][10];
    int in10 [2][10];
};

// ---------------- host-side JAX threefry reproduction (validated R5) ----------------
namespace {

struct KeyPair { uint32_t a, b; };

static inline uint32_t rotl32(uint32_t x, int d) { return (x << d) | (x >> (32 - d)); }

static void tf2x32(uint32_t k0, uint32_t k1, uint32_t x0, uint32_t x1,
                   uint32_t& o0, uint32_t& o1) {
    const uint32_t ks2 = k0 ^ k1 ^ 0x1BD11BDAu;
    const int ra[4] = {13, 15, 26, 6};
    const int rb[4] = {17, 29, 16, 24};
    x0 += k0; x1 += k1;
    for (int i = 0; i < 4; i++) { x0 += x1; x1 = rotl32(x1, ra[i]); x1 ^= x0; }
    x0 += k1; x1 += ks2 + 1u;
    for (int i = 0; i < 4; i++) { x0 += x1; x1 = rotl32(x1, rb[i]); x1 ^= x0; }
    x0 += ks2; x1 += k0 + 2u;
    for (int i = 0; i < 4; i++) { x0 += x1; x1 = rotl32(x1, ra[i]); x1 ^= x0; }
    x0 += k0; x1 += k1 + 3u;
    for (int i = 0; i < 4; i++) { x0 += x1; x1 = rotl32(x1, rb[i]); x1 ^= x0; }
    x0 += k1; x1 += ks2 + 4u;
    for (int i = 0; i < 4; i++) { x0 += x1; x1 = rotl32(x1, ra[i]); x1 ^= x0; }
    x0 += ks2; x1 += k0 + 5u;
    o0 = x0; o1 = x1;
}

static KeyPair split_child(KeyPair k, uint32_t i, uint32_t /*num*/) {
    KeyPair r; tf2x32(k.a, k.b, 0u, i, r.a, r.b); return r;
}
static void bits64(KeyPair k, uint32_t* out /*64*/) {
    for (uint32_t i = 0; i < 64; i++) {
        uint32_t a, b; tf2x32(k.a, k.b, 0u, i, a, b);
        out[i] = a ^ b;
    }
}

static void perm64(KeyPair key, int* out /*64*/) {
    KeyPair sub = split_child(key, 1, 2);
    uint32_t sk[64]; int idx[64];
    bits64(sub, sk);
    for (int i = 0; i < 64; i++) idx[i] = i;
    std::stable_sort(idx, idx + 64, [&](int x, int y) { return sk[x] < sk[y]; });
    for (int i = 0; i < 64; i++) out[i] = idx[i];
}

static void compute_cols(ColsParam& cp) {
    KeyPair base{0u, 42u};
    KeyPair kc[2] = { split_child(base, 0, 2), split_child(base, 1, 2) };
    int p[64];
    for (int c = 0; c < 2; c++) {
        KeyPair K = kc[c];
        KeyPair Kn = split_child(K, 0, 3);
        KeyPair ka = split_child(K, 1, 3);
        KeyPair kb = split_child(K, 2, 3);
        perm64(ka, p); for (int j = 0; j < 25; j++) cp.out25[c][j] = p[j];
        perm64(kb, p); for (int j = 0; j < 25; j++) cp.in25 [c][j] = p[j];
        K = Kn;
        ka = split_child(K, 1, 3);
        kb = split_child(K, 2, 3);
        perm64(ka, p); for (int j = 0; j < 10; j++) cp.out10[c][j] = p[j];
        perm64(kb, p); for (int j = 0; j < 10; j++) cp.in10 [c][j] = p[j];
    }
}

} // namespace

// ---------------- device helpers ----------------
__device__ __forceinline__ float sigf(float x) { return 1.0f / (1.0f + expf(-x)); }
__device__ __forceinline__ void add4(float4& a, const float4 b) {
    a.x += b.x; a.y += b.y; a.z += b.z; a.w += b.w;
}
__device__ __forceinline__ float4 scale4(const float4 a, float s) {
    return make_float4(a.x * s, a.y * s, a.z * s, a.w * s);
}

// ---------------- kernels ----------------

// s1[c][b*50 + t] : t<25 -> out-neighbor cols, t>=25 -> in-neighbor cols
__global__ void k_sample(const int* __restrict__ nodes1, const int* __restrict__ nodes2,
                         const int* __restrict__ nout, const int* __restrict__ nin,
                         ColsParam cp) {
    int c = blockIdx.y, b = blockIdx.x, t = threadIdx.x; // t in [0,50)
    int v = (c ? nodes2 : nodes1)[b];
    int idx = (t < 25) ? nout[v * DEG + cp.out25[c][t]]
                       : nin [v * DEG + cp.in25 [c][t - 25]];
    g_s1[c][b * 50 + t] = idx;
}

// ---- FUSED hop-1 gather + big GEMM ----
// Each block: 64 rows of M1. Phase 1 gathers agg rows [self, mean10(out),
// mean10(in)] into smem (96KB). Phase 2 is the proven R5 scalar SGEMM body
// reading A from the resident smem tile. Output sigmoid -> g_h1.
__global__ __launch_bounds__(256) void k_fused_h1(const int* __restrict__ nout,
                                                  const int* __restrict__ nin,
                                                  const float* __restrict__ feat,
                                                  const float* __restrict__ W,
                                                  ColsParam cp) {
    extern __shared__ float smem[];
    float (*sA)[384] = (float (*)[384])smem;                 // [64][384]
    float (*sB)[128] = (float (*)[128])(smem + 64 * 384);    // [16][128]

    const int tid  = threadIdx.x;
    const int lane = tid & 31;
    const int w    = tid >> 5;       // 8 warps
    const int bm   = blockIdx.x * 64;
    const int c    = bm / S1N;       // block fully inside one chain (12800%64==0)
    const int i0   = bm % S1N;
    const float4* F4 = (const float4*)feat;   // feature row = 32 float4

    // ---- phase 1: gather (warp w owns rows w*8 .. w*8+7) ----
    int s_arr[8], nb_arr[8];
#pragma unroll
    for (int rr = 0; rr < 8; rr++) {
        int r = w * 8 + rr;
        s_arr[rr] = g_s1[c][i0 + r];
    }
#pragma unroll
    for (int rr = 0; rr < 8; rr++) {
        int nb = 0;
        int s = s_arr[rr];
        if (lane < 10)       nb = nout[s * DEG + cp.out10[c][lane]];
        else if (lane < 20)  nb = nin [s * DEG + cp.in10 [c][lane - 10]];
        nb_arr[rr] = nb;
    }
#pragma unroll 2
    for (int rr = 0; rr < 8; rr++) {
        int r = w * 8 + rr;
        int s = s_arr[rr];
        float4 self = F4[(size_t)s * 32 + lane];
        float4 so = make_float4(0.f, 0.f, 0.f, 0.f);
        float4 si = make_float4(0.f, 0.f, 0.f, 0.f);
#pragma unroll
        for (int j = 0; j < 10; j++) {
            int n = __shfl_sync(0xffffffffu, nb_arr[rr], j);
            add4(so, F4[(size_t)n * 32 + lane]);
        }
#pragma unroll
        for (int j = 10; j < 20; j++) {
            int n = __shfl_sync(0xffffffffu, nb_arr[rr], j);
            add4(si, F4[(size_t)n * 32 + lane]);
        }
        float4* row = (float4*)sA[r];
        row[lane]      = self;
        row[32 + lane] = scale4(so, 1.0f / 10.0f);
        row[64 + lane] = scale4(si, 1.0f / 10.0f);
    }
    __syncthreads();

    // ---- phase 2: R5 scalar SGEMM (64x128, BK=16) from smem-resident A ----
    const int tx = tid & 31;   // cols tx*4..tx*4+3
    const int ty = tid >> 5;   // rows ty*8..ty*8+7
    float4 acc[8];
#pragma unroll
    for (int i = 0; i < 8; i++) acc[i] = make_float4(0.f, 0.f, 0.f, 0.f);

    for (int k0 = 0; k0 < 384; k0 += 16) {
        {   // stage W k-slab: 256 threads x 2 float4 = 16x128
            int l = tid, kr = l >> 5, c4 = l & 31;
            *(float4*)&sB[kr][c4 * 4] = *(const float4*)&W[(size_t)(k0 + kr) * 128 + c4 * 4];
            l += 256; kr = l >> 5; c4 = l & 31;
            *(float4*)&sB[kr][c4 * 4] = *(const float4*)&W[(size_t)(k0 + kr) * 128 + c4 * 4];
        }
        __syncthreads();
#pragma unroll
        for (int kk = 0; kk < 16; kk++) {
            float4 bv = *(const float4*)&sB[kk][tx * 4];
#pragma unroll
            for (int i = 0; i < 8; i++) {
                float a = sA[ty * 8 + i][k0 + kk];   // warp-uniform broadcast
                acc[i].x += a * bv.x; acc[i].y += a * bv.y;
                acc[i].z += a * bv.z; acc[i].w += a * bv.w;
            }
        }
        __syncthreads();
    }
#pragma unroll
    for (int i = 0; i < 8; i++) {
        int r = bm + ty * 8 + i;
        float4 v = acc[i];
        v.x = sigf(v.x); v.y = sigf(v.y); v.z = sigf(v.z); v.w = sigf(v.w);
        *(float4*)&g_h1[(size_t)r * 128 + tx * 4] = v;
    }
}

// hop-0 aggregation (unchanged R5)
__global__ __launch_bounds__(128) void k_agg_hop0(const int* __restrict__ nodes1,
                                                  const int* __restrict__ nodes2,
                                                  const float* __restrict__ feat) {
    int c = blockIdx.y, b = blockIdx.x, f = threadIdx.x;
    int v = (c ? nodes2 : nodes1)[b];
    const int* s1 = &g_s1[c][b * 50];
    float self = feat[(size_t)v * FD + f];
    float so = 0.f, si = 0.f;
#pragma unroll 5
    for (int j = 0; j < 25; j++)  so += feat[(size_t)s1[j] * FD + f];
#pragma unroll 5
    for (int j = 25; j < 50; j++) si += feat[(size_t)s1[j] * FD + f];
    float* o = g_agg0 + (size_t)(c * BB + b) * 384;
    o[f]       = self;
    o[128 + f] = so / 25.0f;
    o[256 + f] = si / 25.0f;
}

// small scalar SGEMM body for the tail GEMMs (unchanged R5)
template <int BM, int TM>
__device__ __forceinline__ void sgemm_sig_body(const float* __restrict__ A,
                                               const float* __restrict__ W,
                                               float* __restrict__ C,
                                               int M, int bm) {
    __shared__ float sA[16][BM + 1];
    __shared__ float sB[16][128];
    int tid = threadIdx.x;
    int tx = tid & 31;
    int ty = tid >> 5;
    float4 acc[TM];
#pragma unroll
    for (int i = 0; i < TM; i++) acc[i] = make_float4(0.f, 0.f, 0.f, 0.f);

    for (int k0 = 0; k0 < 384; k0 += 16) {
        if (tid < BM * 4) {
            int r = tid >> 2, kq = tid & 3;
            float4 v = *(const float4*)&A[(size_t)(bm + r) * 384 + k0 + kq * 4];
            sA[kq * 4 + 0][r] = v.x; sA[kq * 4 + 1][r] = v.y;
            sA[kq * 4 + 2][r] = v.z; sA[kq * 4 + 3][r] = v.w;
        }
        {
            int l = tid, kr = l >> 5, c4 = l & 31;
            *(float4*)&sB[kr][c4 * 4] = *(const float4*)&W[(size_t)(k0 + kr) * 128 + c4 * 4];
            l += 256; kr = l >> 5; c4 = l & 31;
            *(float4*)&sB[kr][c4 * 4] = *(const float4*)&W[(size_t)(k0 + kr) * 128 + c4 * 4];
        }
        __syncthreads();
#pragma unroll
        for (int kk = 0; kk < 16; kk++) {
            float4 bv = *(const float4*)&sB[kk][tx * 4];
#pragma unroll
            for (int i = 0; i < TM; i++) {
                float a = sA[kk][ty * TM + i];
                acc[i].x += a * bv.x; acc[i].y += a * bv.y;
                acc[i].z += a * bv.z; acc[i].w += a * bv.w;
            }
        }
        __syncthreads();
    }
#pragma unroll
    for (int i = 0; i < TM; i++) {
        int r = bm + ty * TM + i;
        if (r < M) {
            float4 v = acc[i];
            v.x = sigf(v.x); v.y = sigf(v.y); v.z = sigf(v.z); v.w = sigf(v.w);
            *(float4*)&C[(size_t)r * 128 + tx * 4] = v;
        }
    }
}

__global__ __launch_bounds__(256) void k_gemm_h0(const float* __restrict__ W) {
    sgemm_sig_body<16, 2>(g_agg0, W, g_h0, 2 * BB, blockIdx.x * 16);
}
__global__ __launch_bounds__(256) void k_gemm_heads(const float* __restrict__ Wm,
                                                    const float* __restrict__ Ws,
                                                    const float* __restrict__ Wp) {
    const float* W = (blockIdx.z == 0) ? Wm : (blockIdx.z == 1) ? Ws : Wp;
    sgemm_sig_body<16, 2>(g_aggL1, W, g_head[blockIdx.z], 2 * BB, blockIdx.x * 16);
}

__global__ __launch_bounds__(128) void k_aggL1() {
    int c = blockIdx.y, b = blockIdx.x, f = threadIdx.x;
    const float* h1 = g_h1 + (size_t)(c * S1N + b * 50) * 128;
    float self = g_h0[(size_t)(c * BB + b) * 128 + f];
    float s0 = 0.f, s1v = 0.f;
#pragma unroll 5
    for (int j = 0; j < 25; j++)  s0  += h1[(size_t)j * 128 + f];
#pragma unroll 5
    for (int j = 25; j < 50; j++) s1v += h1[(size_t)j * 128 + f];
    float* o = g_aggL1 + (size_t)(c * BB + b) * 384;
    o[f]       = self;
    o[128 + f] = s0  / 25.0f;
    o[256 + f] = s1v / 25.0f;
}

__global__ __launch_bounds__(256) void k_final(const float* __restrict__ Wm,
                                               const float* __restrict__ Ws,
                                               const float* __restrict__ Wp,
                                               float* __restrict__ out) {
    __shared__ float sW[128 * 64];
    __shared__ float sH[16 * 128];
    int slot = blockIdx.x, rt = blockIdx.y, tid = threadIdx.x;
    int chain = slot / 3, head = slot % 3;
    const float* Wd = (head == 0) ? Wm : (head == 1) ? Ws : Wp;
    const float* H = &g_head[head][(size_t)(chain * BB + rt * 16) * 128];
    for (int l = tid; l < 128 * 64; l += 256) sW[l] = Wd[l];
    for (int l = tid; l < 16 * 128; l += 256) sH[l] = H[l];
    __syncthreads();
    int d = tid & 63, rg = tid >> 6;
#pragma unroll
    for (int ii = 0; ii < 4; ii++) {
        int r = rg * 4 + ii;
        float acc = 0.f;
#pragma unroll 8
        for (int k = 0; k < 128; k++) acc += sH[r * 128 + k] * sW[k * 64 + d];
        out[((size_t)slot * BB + rt * 16 + r) * 64 + d] = acc;
    }
}

// ---------------- launcher ----------------
extern "C" void kernel_launch(void* const* d_in, const int* in_sizes, int n_in,
                              void* d_out, int out_size) {
    (void)in_sizes; (void)n_in; (void)out_size;
    const int*   nodes1 = (const int*)  d_in[0];
    const int*   nodes2 = (const int*)  d_in[1];
    const int*   nout   = (const int*)  d_in[2];
    const int*   nin    = (const int*)  d_in[3];
    const float* feat   = (const float*)d_in[4];
    const float* W_in   = (const float*)d_in[5];
    const float* W_mean = (const float*)d_in[6];
    const float* W_std  = (const float*)d_in[7];
    const float* W_pi   = (const float*)d_in[8];
    const float* Wd_mean = (const float*)d_in[11];
    const float* Wd_std  = (const float*)d_in[12];
    const float* Wd_pi   = (const float*)d_in[13];
    float* out = (float*)d_out;

    ColsParam cp;
    compute_cols(cp);

    // allow 104KB dynamic smem for the fused kernel (idempotent)
    cudaFuncSetAttribute(k_fused_h1, cudaFuncAttributeMaxDynamicSharedMemorySize,
                         SMEM_FUSED);

    k_sample   <<<dim3(BB, 2), 50>>>(nodes1, nodes2, nout, nin, cp);
    k_agg_hop0 <<<dim3(BB, 2), 128>>>(nodes1, nodes2, feat);
    k_fused_h1 <<<M1 / 64, 256, SMEM_FUSED>>>(nout, nin, feat, W_in, cp);
    k_gemm_h0  <<<(2 * BB) / 16, 256>>>(W_in);
    k_aggL1    <<<dim3(BB, 2), 128>>>();
    k_gemm_heads<<<dim3((2 * BB) / 16, 1, 3), 256>>>(W_mean, W_std, W_pi);
    k_final    <<<dim3(6, BB / 16), 256>>>(Wd_mean, Wd_std, Wd_pi, out);
}

// round 12
// speedup vs baseline: 1.2941x; 1.2941x over previous
#include <cuda_runtime.h>
#include <cstdint>
#include <cstddef>
#include <algorithm>

// ---------------- problem constants ----------------
#define BB   256        // batch
#define FD   128        // feature dim (also E)
#define DEG  64         // max degree
#define S1N  (BB * 50)  // 12800 rows per chain at hop-1
#define M1   (2 * S1N)  // 25600 rows (both chains) for the big GEMM

// ---------------- device scratch (static, no runtime alloc) ----------------
__device__ int   g_s1[2][S1N];
__device__ float g_agg1[(size_t)M1 * 384];      // hop1 agg (39.3 MB)
__device__ float g_h1  [(size_t)M1 * 128];      // hop1 hidden
__device__ float g_agg0[(size_t)2 * BB * 384];  // hop0 agg
__device__ float g_h0  [(size_t)2 * BB * 128];  // hop0 hidden
__device__ float g_aggL1[(size_t)2 * BB * 384]; // layer-1 agg
__device__ float g_head[3][(size_t)2 * BB * 128]; // mean/std/pi hidden

struct ColsParam {
    int out25[2][25];
    int in25 [2][25];
    int out10[2][10];
    int in10 [2][10];
};

// ---------------- host-side JAX threefry reproduction (validated R5) ----------------
namespace {

struct KeyPair { uint32_t a, b; };

static inline uint32_t rotl32(uint32_t x, int d) { return (x << d) | (x >> (32 - d)); }

static void tf2x32(uint32_t k0, uint32_t k1, uint32_t x0, uint32_t x1,
                   uint32_t& o0, uint32_t& o1) {
    const uint32_t ks2 = k0 ^ k1 ^ 0x1BD11BDAu;
    const int ra[4] = {13, 15, 26, 6};
    const int rb[4] = {17, 29, 16, 24};
    x0 += k0; x1 += k1;
    for (int i = 0; i < 4; i++) { x0 += x1; x1 = rotl32(x1, ra[i]); x1 ^= x0; }
    x0 += k1; x1 += ks2 + 1u;
    for (int i = 0; i < 4; i++) { x0 += x1; x1 = rotl32(x1, rb[i]); x1 ^= x0; }
    x0 += ks2; x1 += k0 + 2u;
    for (int i = 0; i < 4; i++) { x0 += x1; x1 = rotl32(x1, ra[i]); x1 ^= x0; }
    x0 += k0; x1 += k1 + 3u;
    for (int i = 0; i < 4; i++) { x0 += x1; x1 = rotl32(x1, rb[i]); x1 ^= x0; }
    x0 += k1; x1 += ks2 + 4u;
    for (int i = 0; i < 4; i++) { x0 += x1; x1 = rotl32(x1, ra[i]); x1 ^= x0; }
    x0 += ks2; x1 += k0 + 5u;
    o0 = x0; o1 = x1;
}

static KeyPair split_child(KeyPair k, uint32_t i, uint32_t /*num*/) {
    KeyPair r; tf2x32(k.a, k.b, 0u, i, r.a, r.b); return r;
}
static void bits64(KeyPair k, uint32_t* out /*64*/) {
    for (uint32_t i = 0; i < 64; i++) {
        uint32_t a, b; tf2x32(k.a, k.b, 0u, i, a, b);
        out[i] = a ^ b;
    }
}

static void perm64(KeyPair key, int* out /*64*/) {
    KeyPair sub = split_child(key, 1, 2);
    uint32_t sk[64]; int idx[64];
    bits64(sub, sk);
    for (int i = 0; i < 64; i++) idx[i] = i;
    std::stable_sort(idx, idx + 64, [&](int x, int y) { return sk[x] < sk[y]; });
    for (int i = 0; i < 64; i++) out[i] = idx[i];
}

static void compute_cols(ColsParam& cp) {
    KeyPair base{0u, 42u};
    KeyPair kc[2] = { split_child(base, 0, 2), split_child(base, 1, 2) };
    int p[64];
    for (int c = 0; c < 2; c++) {
        KeyPair K = kc[c];
        KeyPair Kn = split_child(K, 0, 3);
        KeyPair ka = split_child(K, 1, 3);
        KeyPair kb = split_child(K, 2, 3);
        perm64(ka, p); for (int j = 0; j < 25; j++) cp.out25[c][j] = p[j];
        perm64(kb, p); for (int j = 0; j < 25; j++) cp.in25 [c][j] = p[j];
        K = Kn;
        ka = split_child(K, 1, 3);
        kb = split_child(K, 2, 3);
        perm64(ka, p); for (int j = 0; j < 10; j++) cp.out10[c][j] = p[j];
        perm64(kb, p); for (int j = 0; j < 10; j++) cp.in10 [c][j] = p[j];
    }
}

} // namespace

// ---------------- device helpers ----------------
__device__ __forceinline__ float sigf(float x) { return 1.0f / (1.0f + expf(-x)); }

// ---------------- kernels ----------------

// s1[c][b*50 + t] : t<25 -> out-neighbor cols, t>=25 -> in-neighbor cols
__global__ void k_sample(const int* __restrict__ nodes1, const int* __restrict__ nodes2,
                         const int* __restrict__ nout, const int* __restrict__ nin,
                         ColsParam cp) {
    int c = blockIdx.y, b = blockIdx.x, t = threadIdx.x; // t in [0,50)
    int v = (c ? nodes2 : nodes1)[b];
    int idx = (t < 25) ? nout[v * DEG + cp.out25[c][t]]
                       : nin [v * DEG + cp.in25 [c][t - 25]];
    g_s1[c][b * 50 + t] = idx;
}

// hop-1 aggregation (proven R5 version)
__global__ __launch_bounds__(128) void k_agg_hop1(const int* __restrict__ nout,
                                                  const int* __restrict__ nin,
                                                  const float* __restrict__ feat,
                                                  ColsParam cp) {
    int c = blockIdx.y;
    int i = blockIdx.x;
    int f = threadIdx.x;
    __shared__ int nb[20];
    int s = g_s1[c][i];
    if (f < 10)       nb[f] = nout[s * DEG + cp.out10[c][f]];
    else if (f < 20)  nb[f] = nin [s * DEG + cp.in10 [c][f - 10]];
    __syncthreads();
    float self = feat[(size_t)s * FD + f];
    float so = 0.f, si = 0.f;
#pragma unroll
    for (int j = 0; j < 10; j++)  so += feat[(size_t)nb[j] * FD + f];
#pragma unroll
    for (int j = 10; j < 20; j++) si += feat[(size_t)nb[j] * FD + f];
    float* o = g_agg1 + ((size_t)c * S1N + i) * 384;
    o[f]        = self;
    o[128 + f]  = so / 10.0f;
    o[256 + f]  = si / 10.0f;
}

// hop-0 aggregation (proven R5 version)
__global__ __launch_bounds__(128) void k_agg_hop0(const int* __restrict__ nodes1,
                                                  const int* __restrict__ nodes2,
                                                  const float* __restrict__ feat) {
    int c = blockIdx.y, b = blockIdx.x, f = threadIdx.x;
    int v = (c ? nodes2 : nodes1)[b];
    const int* s1 = &g_s1[c][b * 50];
    float self = feat[(size_t)v * FD + f];
    float so = 0.f, si = 0.f;
#pragma unroll 5
    for (int j = 0; j < 25; j++)  so += feat[(size_t)s1[j] * FD + f];
#pragma unroll 5
    for (int j = 25; j < 50; j++) si += feat[(size_t)s1[j] * FD + f];
    float* o = g_agg0 + (size_t)(c * BB + b) * 384;
    o[f]       = self;
    o[128 + f] = so / 25.0f;
    o[256 + f] = si / 25.0f;
}

// ---- BIG GEMM (proven R5 scalar body, 68.6us @ FFMA roofline) ----
__global__ __launch_bounds__(256) void k_gemm_h1(const float* __restrict__ W) {
    __shared__ float sA[16][65];
    __shared__ float sB[16][128];
    const float* A = g_agg1;
    int bm  = blockIdx.x * 64;
    int tid = threadIdx.x;
    int tx = tid & 31;
    int ty = tid >> 5;
    float4 acc[8];
#pragma unroll
    for (int i = 0; i < 8; i++) acc[i] = make_float4(0.f, 0.f, 0.f, 0.f);

    for (int k0 = 0; k0 < 384; k0 += 16) {
        {
            int r = tid >> 2, kq = tid & 3;
            float4 v = *(const float4*)&A[(size_t)(bm + r) * 384 + k0 + kq * 4];
            sA[kq * 4 + 0][r] = v.x; sA[kq * 4 + 1][r] = v.y;
            sA[kq * 4 + 2][r] = v.z; sA[kq * 4 + 3][r] = v.w;
        }
        {
            int l = tid, kr = l >> 5, c4 = l & 31;
            *(float4*)&sB[kr][c4 * 4] = *(const float4*)&W[(size_t)(k0 + kr) * 128 + c4 * 4];
            l += 256; kr = l >> 5; c4 = l & 31;
            *(float4*)&sB[kr][c4 * 4] = *(const float4*)&W[(size_t)(k0 + kr) * 128 + c4 * 4];
        }
        __syncthreads();
#pragma unroll
        for (int kk = 0; kk < 16; kk++) {
            float4 bv = *(const float4*)&sB[kk][tx * 4];
#pragma unroll
            for (int i = 0; i < 8; i++) {
                float a = sA[kk][ty * 8 + i];
                acc[i].x += a * bv.x; acc[i].y += a * bv.y;
                acc[i].z += a * bv.z; acc[i].w += a * bv.w;
            }
        }
        __syncthreads();
    }
#pragma unroll
    for (int i = 0; i < 8; i++) {
        int r = bm + ty * 8 + i;
        float4 v = acc[i];
        v.x = sigf(v.x); v.y = sigf(v.y); v.z = sigf(v.z); v.w = sigf(v.w);
        *(float4*)&g_h1[(size_t)r * 128 + tx * 4] = v;
    }
}

// ---- NEW latency-optimized tail GEMM: thread-per-output-element ----
// Block: 256 threads = 2 rows x 128 cols. A rows staged in smem, straight
// 384-deep k-loop (unroll 8 -> MLP 8), W read coalesced & L1/L2-cached.
__device__ __forceinline__ void gemm_rows2_body(const float* __restrict__ A,
                                                const float* __restrict__ W,
                                                float* __restrict__ C,
                                                int b0) {
    __shared__ float sA[2][384];
    int tid = threadIdx.x;
    // stage 2 rows (768 floats) coalesced
    for (int l = tid; l < 768; l += 256)
        sA[0][l] = A[(size_t)b0 * 384 + l];
    __syncthreads();
    int r = tid >> 7, j = tid & 127;
    float acc = 0.f;
#pragma unroll 8
    for (int k = 0; k < 384; k++)
        acc += sA[r][k] * W[(size_t)k * 128 + j];
    C[(size_t)(b0 + r) * 128 + j] = sigf(acc);
}

__global__ __launch_bounds__(256) void k_gemm_h0(const float* __restrict__ W) {
    gemm_rows2_body(g_agg0, W, g_h0, blockIdx.x * 2);
}
__global__ __launch_bounds__(256) void k_gemm_heads(const float* __restrict__ Wm,
                                                    const float* __restrict__ Ws,
                                                    const float* __restrict__ Wp) {
    const float* W = (blockIdx.z == 0) ? Wm : (blockIdx.z == 1) ? Ws : Wp;
    gemm_rows2_body(g_aggL1, W, g_head[blockIdx.z], blockIdx.x * 2);
}

// layer-1 aggregation (proven R5 version)
__global__ __launch_bounds__(128) void k_aggL1() {
    int c = blockIdx.y, b = blockIdx.x, f = threadIdx.x;
    const float* h1 = g_h1 + (size_t)(c * S1N + b * 50) * 128;
    float self = g_h0[(size_t)(c * BB + b) * 128 + f];
    float s0 = 0.f, s1v = 0.f;
#pragma unroll 5
    for (int j = 0; j < 25; j++)  s0  += h1[(size_t)j * 128 + f];
#pragma unroll 5
    for (int j = 25; j < 50; j++) s1v += h1[(size_t)j * 128 + f];
    float* o = g_aggL1 + (size_t)(c * BB + b) * 384;
    o[f]       = self;
    o[128 + f] = s0  / 25.0f;
    o[256 + f] = s1v / 25.0f;
}

// final projection: thread-per-element, 4 rows x 64 cols per block of 256
__global__ __launch_bounds__(256) void k_final(const float* __restrict__ Wm,
                                               const float* __restrict__ Ws,
                                               const float* __restrict__ Wp,
                                               float* __restrict__ out) {
    __shared__ float sH[4][128];
    int slot = blockIdx.x, rt = blockIdx.y, tid = threadIdx.x;
    int chain = slot / 3, head = slot % 3;
    const float* Wd = (head == 0) ? Wm : (head == 1) ? Ws : Wp;
    const float* H = &g_head[head][(size_t)(chain * BB + rt * 4) * 128];
    for (int l = tid; l < 4 * 128; l += 256) sH[0][l] = H[l];
    __syncthreads();
    int r = tid >> 6, d = tid & 63;
    float acc = 0.f;
#pragma unroll 8
    for (int k = 0; k < 128; k++) acc += sH[r][k] * Wd[(size_t)k * 64 + d];
    out[((size_t)slot * BB + rt * 4 + r) * 64 + d] = acc;
}

// ---------------- launcher ----------------
extern "C" void kernel_launch(void* const* d_in, const int* in_sizes, int n_in,
                              void* d_out, int out_size) {
    (void)in_sizes; (void)n_in; (void)out_size;
    const int*   nodes1 = (const int*)  d_in[0];
    const int*   nodes2 = (const int*)  d_in[1];
    const int*   nout   = (const int*)  d_in[2];
    const int*   nin    = (const int*)  d_in[3];
    const float* feat   = (const float*)d_in[4];
    const float* W_in   = (const float*)d_in[5];
    const float* W_mean = (const float*)d_in[6];
    const float* W_std  = (const float*)d_in[7];
    const float* W_pi   = (const float*)d_in[8];
    const float* Wd_mean = (const float*)d_in[11];
    const float* Wd_std  = (const float*)d_in[12];
    const float* Wd_pi   = (const float*)d_in[13];
    float* out = (float*)d_out;

    ColsParam cp;
    compute_cols(cp);

    k_sample   <<<dim3(BB, 2),   50>>>(nodes1, nodes2, nout, nin, cp);
    k_agg_hop1 <<<dim3(S1N, 2), 128>>>(nout, nin, feat, cp);
    k_agg_hop0 <<<dim3(BB, 2),  128>>>(nodes1, nodes2, feat);
    k_gemm_h1  <<<M1 / 64, 256>>>(W_in);
    k_gemm_h0  <<<BB, 256>>>(W_in);                       // 256 blocks (2 rows each)
    k_aggL1    <<<dim3(BB, 2), 128>>>();
    k_gemm_heads<<<dim3(BB, 1, 3), 256>>>(W_mean, W_std, W_pi);  // 768 blocks
    k_final    <<<dim3(6, BB / 4), 256>>>(Wd_mean, Wd_std, Wd_pi, out);  // 384 blocks
}

// round 17
// speedup vs baseline: 1.3819x; 1.0679x over previous
#include <cuda_runtime.h>
#include <cstdint>
#include <cstddef>
#include <algorithm>

// ---------------- problem constants ----------------
#define BB   256        // batch
#define FD   128        // feature dim (also E)
#define DEG  64         // max degree
#define S1N  (BB * 50)  // 12800 rows per chain at hop-1
#define M1   (2 * S1N)  // 25600 rows (both chains) for the big GEMM

// ---------------- device scratch (static, no runtime alloc) ----------------
__device__ int   g_s1[2][S1N];
__device__ float g_agg1[(size_t)M1 * 384];      // hop1 agg (39.3 MB)
__device__ float g_h1  [(size_t)M1 * 128];      // hop1 hidden
__device__ float g_agg0[(size_t)2 * BB * 384];  // hop0 agg
__device__ float g_h0  [(size_t)2 * BB * 128];  // hop0 hidden
__device__ float g_aggL1[(size_t)2 * BB * 384]; // layer-1 agg
__device__ float g_head[3][(size_t)2 * BB * 128]; // mean/std/pi hidden

struct ColsParam {
    int out25[2][25];
    int in25 [2][25];
    int out10[2][10];
    int in10 [2][10];
};

// ---------------- host-side JAX threefry reproduction (validated R5) ----------------
namespace {

struct KeyPair { uint32_t a, b; };

static inline uint32_t rotl32(uint32_t x, int d) { return (x << d) | (x >> (32 - d)); }

static void tf2x32(uint32_t k0, uint32_t k1, uint32_t x0, uint32_t x1,
                   uint32_t& o0, uint32_t& o1) {
    const uint32_t ks2 = k0 ^ k1 ^ 0x1BD11BDAu;
    const int ra[4] = {13, 15, 26, 6};
    const int rb[4] = {17, 29, 16, 24};
    x0 += k0; x1 += k1;
    for (int i = 0; i < 4; i++) { x0 += x1; x1 = rotl32(x1, ra[i]); x1 ^= x0; }
    x0 += k1; x1 += ks2 + 1u;
    for (int i = 0; i < 4; i++) { x0 += x1; x1 = rotl32(x1, rb[i]); x1 ^= x0; }
    x0 += ks2; x1 += k0 + 2u;
    for (int i = 0; i < 4; i++) { x0 += x1; x1 = rotl32(x1, ra[i]); x1 ^= x0; }
    x0 += k0; x1 += k1 + 3u;
    for (int i = 0; i < 4; i++) { x0 += x1; x1 = rotl32(x1, rb[i]); x1 ^= x0; }
    x0 += k1; x1 += ks2 + 4u;
    for (int i = 0; i < 4; i++) { x0 += x1; x1 = rotl32(x1, ra[i]); x1 ^= x0; }
    x0 += ks2; x1 += k0 + 5u;
    o0 = x0; o1 = x1;
}

static KeyPair split_child(KeyPair k, uint32_t i, uint32_t /*num*/) {
    KeyPair r; tf2x32(k.a, k.b, 0u, i, r.a, r.b); return r;
}
static void bits64(KeyPair k, uint32_t* out /*64*/) {
    for (uint32_t i = 0; i < 64; i++) {
        uint32_t a, b; tf2x32(k.a, k.b, 0u, i, a, b);
        out[i] = a ^ b;
    }
}

static void perm64(KeyPair key, int* out /*64*/) {
    KeyPair sub = split_child(key, 1, 2);
    uint32_t sk[64]; int idx[64];
    bits64(sub, sk);
    for (int i = 0; i < 64; i++) idx[i] = i;
    std::stable_sort(idx, idx + 64, [&](int x, int y) { return sk[x] < sk[y]; });
    for (int i = 0; i < 64; i++) out[i] = idx[i];
}

static void compute_cols(ColsParam& cp) {
    KeyPair base{0u, 42u};
    KeyPair kc[2] = { split_child(base, 0, 2), split_child(base, 1, 2) };
    int p[64];
    for (int c = 0; c < 2; c++) {
        KeyPair K = kc[c];
        KeyPair Kn = split_child(K, 0, 3);
        KeyPair ka = split_child(K, 1, 3);
        KeyPair kb = split_child(K, 2, 3);
        perm64(ka, p); for (int j = 0; j < 25; j++) cp.out25[c][j] = p[j];
        perm64(kb, p); for (int j = 0; j < 25; j++) cp.in25 [c][j] = p[j];
        K = Kn;
        ka = split_child(K, 1, 3);
        kb = split_child(K, 2, 3);
        perm64(ka, p); for (int j = 0; j < 10; j++) cp.out10[c][j] = p[j];
        perm64(kb, p); for (int j = 0; j < 10; j++) cp.in10 [c][j] = p[j];
    }
}

} // namespace

// ---------------- device helpers ----------------
__device__ __forceinline__ float sigf(float x) { return 1.0f / (1.0f + expf(-x)); }
__device__ __forceinline__ void add4(float4& a, const float4 b) {
    a.x += b.x; a.y += b.y; a.z += b.z; a.w += b.w;
}
__device__ __forceinline__ float4 scale4(const float4 a, float s) {
    return make_float4(a.x * s, a.y * s, a.z * s, a.w * s);
}

// ---------------- kernels ----------------

// s1[c][b*50 + t] : t<25 -> out-neighbor cols, t>=25 -> in-neighbor cols
__global__ void k_sample(const int* __restrict__ nodes1, const int* __restrict__ nodes2,
                         const int* __restrict__ nout, const int* __restrict__ nin,
                         ColsParam cp) {
    int c = blockIdx.y, b = blockIdx.x, t = threadIdx.x; // t in [0,50)
    int v = (c ? nodes2 : nodes1)[b];
    int idx = (t < 25) ? nout[v * DEG + cp.out25[c][t]]
                       : nin [v * DEG + cp.in25 [c][t - 25]];
    g_s1[c][b * 50 + t] = idx;
}

// hop-1 aggregation: warp per row, float4 lanes, shfl-broadcast indices.
// One warp instruction = one full 512B feature row; 21 independent LDG.128
// per lane in flight. Summation order per element identical to scalar version.
__global__ __launch_bounds__(256) void k_agg_hop1(const int* __restrict__ nout,
                                                  const int* __restrict__ nin,
                                                  const float* __restrict__ feat,
                                                  ColsParam cp) {
    int c = blockIdx.y;
    int w = threadIdx.x >> 5, lane = threadIdx.x & 31;
    int i = blockIdx.x * 8 + w;   // 0..S1N-1
    int s = g_s1[c][i];
    int nb = 0;
    if (lane < 10)      nb = nout[s * DEG + cp.out10[c][lane]];
    else if (lane < 20) nb = nin [s * DEG + cp.in10 [c][lane - 10]];

    const float4* F = (const float4*)feat;      // row stride 32 float4
    float4 self = F[(size_t)s * 32 + lane];
    float4 so = make_float4(0.f, 0.f, 0.f, 0.f);
    float4 si = make_float4(0.f, 0.f, 0.f, 0.f);
#pragma unroll
    for (int j = 0; j < 10; j++) {
        int n = __shfl_sync(0xffffffffu, nb, j);
        add4(so, F[(size_t)n * 32 + lane]);
    }
#pragma unroll
    for (int j = 10; j < 20; j++) {
        int n = __shfl_sync(0xffffffffu, nb, j);
        add4(si, F[(size_t)n * 32 + lane]);
    }
    float4* o = (float4*)(g_agg1 + ((size_t)c * S1N + i) * 384);
    o[lane]      = self;
    o[32 + lane] = scale4(so, 1.0f / 10.0f);
    o[64 + lane] = scale4(si, 1.0f / 10.0f);
}

// hop-0 aggregation (proven R5 version)
__global__ __launch_bounds__(128) void k_agg_hop0(const int* __restrict__ nodes1,
                                                  const int* __restrict__ nodes2,
                                                  const float* __restrict__ feat) {
    int c = blockIdx.y, b = blockIdx.x, f = threadIdx.x;
    int v = (c ? nodes2 : nodes1)[b];
    const int* s1 = &g_s1[c][b * 50];
    float self = feat[(size_t)v * FD + f];
    float so = 0.f, si = 0.f;
#pragma unroll 5
    for (int j = 0; j < 25; j++)  so += feat[(size_t)s1[j] * FD + f];
#pragma unroll 5
    for (int j = 25; j < 50; j++) si += feat[(size_t)s1[j] * FD + f];
    float* o = g_agg0 + (size_t)(c * BB + b) * 384;
    o[f]       = self;
    o[128 + f] = so / 25.0f;
    o[256 + f] = si / 25.0f;
}

// ---- BIG GEMM (proven R5 scalar body, ~66.5us @ FFMA roofline) ----
__global__ __launch_bounds__(256) void k_gemm_h1(const float* __restrict__ W) {
    __shared__ float sA[16][65];
    __shared__ float sB[16][128];
    const float* A = g_agg1;
    int bm  = blockIdx.x * 64;
    int tid = threadIdx.x;
    int tx = tid & 31;
    int ty = tid >> 5;
    float4 acc[8];
#pragma unroll
    for (int i = 0; i < 8; i++) acc[i] = make_float4(0.f, 0.f, 0.f, 0.f);

    for (int k0 = 0; k0 < 384; k0 += 16) {
        {
            int r = tid >> 2, kq = tid & 3;
            float4 v = *(const float4*)&A[(size_t)(bm + r) * 384 + k0 + kq * 4];
            sA[kq * 4 + 0][r] = v.x; sA[kq * 4 + 1][r] = v.y;
            sA[kq * 4 + 2][r] = v.z; sA[kq * 4 + 3][r] = v.w;
        }
        {
            int l = tid, kr = l >> 5, c4 = l & 31;
            *(float4*)&sB[kr][c4 * 4] = *(const float4*)&W[(size_t)(k0 + kr) * 128 + c4 * 4];
            l += 256; kr = l >> 5; c4 = l & 31;
            *(float4*)&sB[kr][c4 * 4] = *(const float4*)&W[(size_t)(k0 + kr) * 128 + c4 * 4];
        }
        __syncthreads();
#pragma unroll
        for (int kk = 0; kk < 16; kk++) {
            float4 bv = *(const float4*)&sB[kk][tx * 4];
#pragma unroll
            for (int i = 0; i < 8; i++) {
                float a = sA[kk][ty * 8 + i];
                acc[i].x += a * bv.x; acc[i].y += a * bv.y;
                acc[i].z += a * bv.z; acc[i].w += a * bv.w;
            }
        }
        __syncthreads();
    }
#pragma unroll
    for (int i = 0; i < 8; i++) {
        int r = bm + ty * 8 + i;
        float4 v = acc[i];
        v.x = sigf(v.x); v.y = sigf(v.y); v.z = sigf(v.z); v.w = sigf(v.w);
        *(float4*)&g_h1[(size_t)r * 128 + tx * 4] = v;
    }
}

// ---- latency-optimized tail GEMM: thread-per-output-element (proven R12) ----
__device__ __forceinline__ void gemm_rows2_body(const float* __restrict__ A,
                                                const float* __restrict__ W,
                                                float* __restrict__ C,
                                                int b0) {
    __shared__ float sA[2][384];
    int tid = threadIdx.x;
    for (int l = tid; l < 768; l += 256)
        sA[0][l] = A[(size_t)b0 * 384 + l];
    __syncthreads();
    int r = tid >> 7, j = tid & 127;
    float acc = 0.f;
#pragma unroll 8
    for (int k = 0; k < 384; k++)
        acc += sA[r][k] * W[(size_t)k * 128 + j];
    C[(size_t)(b0 + r) * 128 + j] = sigf(acc);
}

__global__ __launch_bounds__(256) void k_gemm_h0(const float* __restrict__ W) {
    gemm_rows2_body(g_agg0, W, g_h0, blockIdx.x * 2);
}
__global__ __launch_bounds__(256) void k_gemm_heads(const float* __restrict__ Wm,
                                                    const float* __restrict__ Ws,
                                                    const float* __restrict__ Wp) {
    const float* W = (blockIdx.z == 0) ? Wm : (blockIdx.z == 1) ? Ws : Wp;
    gemm_rows2_body(g_aggL1, W, g_head[blockIdx.z], blockIdx.x * 2);
}

// layer-1 aggregation (proven R5 version)
__global__ __launch_bounds__(128) void k_aggL1() {
    int c = blockIdx.y, b = blockIdx.x, f = threadIdx.x;
    const float* h1 = g_h1 + (size_t)(c * S1N + b * 50) * 128;
    float self = g_h0[(size_t)(c * BB + b) * 128 + f];
    float s0 = 0.f, s1v = 0.f;
#pragma unroll 5
    for (int j = 0; j < 25; j++)  s0  += h1[(size_t)j * 128 + f];
#pragma unroll 5
    for (int j = 25; j < 50; j++) s1v += h1[(size_t)j * 128 + f];
    float* o = g_aggL1 + (size_t)(c * BB + b) * 384;
    o[f]       = self;
    o[128 + f] = s0  / 25.0f;
    o[256 + f] = s1v / 25.0f;
}

// final projection: thread-per-element, 4 rows x 64 cols per block of 256
__global__ __launch_bounds__(256) void k_final(const float* __restrict__ Wm,
                                               const float* __restrict__ Ws,
                                               const float* __restrict__ Wp,
                                               float* __restrict__ out) {
    __shared__ float sH[4][128];
    int slot = blockIdx.x, rt = blockIdx.y, tid = threadIdx.x;
    int chain = slot / 3, head = slot % 3;
    const float* Wd = (head == 0) ? Wm : (head == 1) ? Ws : Wp;
    const float* H = &g_head[head][(size_t)(chain * BB + rt * 4) * 128];
    for (int l = tid; l < 4 * 128; l += 256) sH[0][l] = H[l];
    __syncthreads();
    int r = tid >> 6, d = tid & 63;
    float acc = 0.f;
#pragma unroll 8
    for (int k = 0; k < 128; k++) acc += sH[r][k] * Wd[(size_t)k * 64 + d];
    out[((size_t)slot * BB + rt * 4 + r) * 64 + d] = acc;
}

// ---------------- launcher ----------------
extern "C" void kernel_launch(void* const* d_in, const int* in_sizes, int n_in,
                              void* d_out, int out_size) {
    (void)in_sizes; (void)n_in; (void)out_size;
    const int*   nodes1 = (const int*)  d_in[0];
    const int*   nodes2 = (const int*)  d_in[1];
    const int*   nout   = (const int*)  d_in[2];
    const int*   nin    = (const int*)  d_in[3];
    const float* feat   = (const float*)d_in[4];
    const float* W_in   = (const float*)d_in[5];
    const float* W_mean = (const float*)d_in[6];
    const float* W_std  = (const float*)d_in[7];
    const float* W_pi   = (const float*)d_in[8];
    const float* Wd_mean = (const float*)d_in[11];
    const float* Wd_std  = (const float*)d_in[12];
    const float* Wd_pi   = (const float*)d_in[13];
    float* out = (float*)d_out;

    ColsParam cp;
    compute_cols(cp);

    k_sample   <<<dim3(BB, 2),      50>>>(nodes1, nodes2, nout, nin, cp);
    k_agg_hop1 <<<dim3(S1N / 8, 2), 256>>>(nout, nin, feat, cp);
    k_agg_hop0 <<<dim3(BB, 2),     128>>>(nodes1, nodes2, feat);
    k_gemm_h1  <<<M1 / 64, 256>>>(W_in);
    k_gemm_h0  <<<BB, 256>>>(W_in);
    k_aggL1    <<<dim3(BB, 2), 128>>>();
    k_gemm_heads<<<dim3(BB, 1, 3), 256>>>(W_mean, W_std, W_pi);
    k_final    <<<dim3(6, BB / 4), 256>>>(Wd_mean, Wd_std, Wd_pi, out);
}